// round 9
// baseline (speedup 1.0000x reference)
#include <cuda_runtime.h>

// Round 9: kill the 8x gather amplification.
//  - extract_kernel streams enc[:, :, 15] into compact lastF[v][c] (device scratch):
//    winner-feature gather becomes lane-contiguous (1 line/warp vs 128 sectors/row).
//  - main kernel is round 7 verbatim (best known) except gather reads lastF.
namespace {

constexpr int GRID_H = 13;
constexpr int GRID_W = 3;
constexpr int G      = GRID_H * GRID_W;   // 39
constexpr int ENC    = 128;
constexpr int TS     = 16;
constexpr int C31    = 16;
constexpr int C11    = 32;
constexpr int SOCD   = 64;
constexpr int KN     = 32;
constexpr int U      = 4;                 // batches per block
constexpr int FPITCH = 129;
constexpr int MAXJ   = U * KN;
constexpr int FCD    = 160;
constexpr int NVEH_MAX = 100000;

__device__ __align__(16) float wT[3 * ENC * C31];     // [kh][ic][oc16]
__device__ __align__(16) float fcwT[FCD * SOCD];      // [f][o]
__device__ __align__(16) float lastF[NVEH_MAX * ENC]; // [v][c] = enc[v][c][TS-1]

__device__ __forceinline__ float lrelu(float x) { return x > 0.0f ? x : 0.1f * x; }

// stream enc[:, :, 15] -> lastF. thread handles 4 channels (MLP=4), writes coalesced.
__global__ __launch_bounds__(256)
void extract_kernel(const float* __restrict__ enc, int nveh)
{
    int i = blockIdx.x * 256 + threadIdx.x;        // i in [0, nveh*32)
    int v = i >> 5, c0 = i & 31;
    if (v < nveh) {
        const float* base = enc + (size_t)v * (ENC * TS) + (TS - 1);
        float f0 = __ldg(base + (c0      ) * TS);
        float f1 = __ldg(base + (c0 + 32 ) * TS);
        float f2 = __ldg(base + (c0 + 64 ) * TS);
        float f3 = __ldg(base + (c0 + 96 ) * TS);
        float* o = lastF + (size_t)v * ENC;
        o[c0] = f0; o[c0 + 32] = f1; o[c0 + 64] = f2; o[c0 + 96] = f3;
    }
}

__global__ void prep_kernel(const float* __restrict__ w31,
                            const float* __restrict__ fcw)
{
    int i = blockIdx.x * 256 + threadIdx.x;
    if (i < 3 * ENC * C31) {
        int kh = i >> 11;
        int r  = i & 2047;
        int ic = r >> 4, oc = r & 15;
        wT[i] = w31[(oc * ENC + ic) * 3 + kh];
    }
    if (i < FCD * SOCD) {
        int f = i >> 6, o = i & 63;
        fcwT[i] = fcw[o * FCD + f];
    }
}

__global__ __launch_bounds__(256, 6)
void csp_kernel(const int*   __restrict__ nb,    // [B,32]
                const int*   __restrict__ gp,    // [N_VEH,2]
                const float* __restrict__ b31,   // [16]
                const float* __restrict__ w11,   // [32,16]
                const float* __restrict__ b11,   // [32]
                const float* __restrict__ fcb,   // [64]
                float*       __restrict__ out,   // [B,64]
                int batch)
{
    __shared__ __align__(16) float featC[32 * FPITCH];   // 16512B; later red[4][64][4]
    __shared__ __align__(16) float yT[32 * 3 * C31];     // 6144B; later p[160][4]
    __shared__ __align__(16) float a1[U * G * C31];      // 9984B; winner ints at start
    __shared__ __align__(16) float w11s[C31 * C11];      // [ic][oc]
    __shared__ float b31s[C31];
    __shared__ float b11s[C11];
    __shared__ int   jOf[U * G];
    __shared__ int   vehG[MAXJ];
    __shared__ int   totCnt;

    const int b0  = blockIdx.x * U;
    const int tid = threadIdx.x;
    const int wid = tid >> 5;
    const int lan = tid & 31;

    // ---- stage small weights / init ----
    for (int i = tid; i < C31 * C11; i += 256) {
        int ic = i >> 5, oc = i & 31;
        w11s[i] = __ldg(w11 + oc * C31 + ic);
    }
    if (tid < C31) b31s[tid] = __ldg(b31 + tid);
    if (tid < C11) b11s[tid] = __ldg(b11 + tid);
    if (tid < U * G) jOf[tid] = -1;
    if (tid == 0) totCnt = 0;
    int* winner = (int*)a1;
    if (tid < U * G) winner[tid] = -1;
    __syncthreads();

    // ---- winners per cell ----
    if (tid < U * KN) {
        int u = tid >> 5, k = tid & 31;
        int b = b0 + u;
        if (b < batch) {
            int v = nb[b * KN + k];
            int x = __ldg(gp + 2 * v), yy = __ldg(gp + 2 * v + 1);
            if (x >= 0 && x < GRID_H && yy >= 0 && yy < GRID_W)
                atomicMax(&winner[u * G + x * GRID_W + yy], k);
        }
    }
    __syncthreads();
    if (tid < U * G) {
        int w = winner[tid];
        if (w >= 0) {
            int u = tid / G;
            int v = nb[(b0 + u) * KN + w];
            int j = atomicAdd(&totCnt, 1);
            jOf[tid] = j;
            vehG[j]  = v;
        }
    }
    __syncthreads();
    const int tot    = totCnt;
    const int ntiles = (tot + 31) >> 5;

    // ---- init a1 = bias (winner scratch dead) ----
    for (int e = tid; e < U * G * C31; e += 256)
        a1[e] = b31s[e & 15];
    __syncthreads();

    // ---- tiles: gather (compact, lane-contiguous) -> conv3x1 -> accumulate a1 ----
    for (int t = 0; t < ntiles; ++t) {
        const int  jBase = t << 5;
        const int  nT    = min(32, tot - jBase);
        const bool last  = (t == ntiles - 1);

        for (int i = tid; i < (nT << 7); i += 256) {
            int s = i >> 7, ic = i & 127;
            int v = vehG[jBase + s];
            featC[s * FPITCH + ic] = __ldg(lastF + (size_t)v * ENC + ic);
        }
        __syncthreads();

        for (int c = wid; c < 12; c += 8) {
            int kh = c >> 2, ocg = c & 3;
            const float4* wr = (const float4*)wT + (kh << 9) + ocg;
            const float*  fr = featC + lan * FPITCH;
            float4 acc = make_float4(0.f, 0.f, 0.f, 0.f);
            #pragma unroll 4
            for (int ic = 0; ic < ENC; ++ic) {
                float4 wv = __ldg(wr + (ic << 2));   // uniform across lanes
                float  f  = fr[ic];
                acc.x += f * wv.x; acc.y += f * wv.y;
                acc.z += f * wv.z; acc.w += f * wv.w;
            }
            if (lan < nT)
                *(float4*)(yT + lan * 48 + (kh << 4) + (ocg << 2)) = acc;
        }
        __syncthreads();

        for (int e = tid; e < U * G * C31; e += 256) {
            int u   = e / (G * C31);
            int r   = e - u * (G * C31);
            int pos = r >> 4, oc = r & 15;
            int h = pos / 3, w = pos - h * 3;
            float val = a1[e];
            #pragma unroll
            for (int dh = -1; dh <= 1; ++dh) {
                int hh = h + dh;
                if ((unsigned)hh < (unsigned)GRID_H) {
                    int j = jOf[u * G + hh * 3 + w];
                    int s = j - jBase;
                    if (s >= 0 && s < nT)
                        val += yT[s * 48 + ((dh + 1) << 4) + oc];
                }
            }
            a1[e] = last ? lrelu(val) : val;
        }
        __syncthreads();
    }
    if (ntiles == 0) {
        for (int e = tid; e < U * G * C31; e += 256)
            a1[e] = lrelu(a1[e]);
        __syncthreads();
    }

    // ---- conv1x1 + lrelu + 3x3/3 maxpool. warp-task=(u,ph), lane=oc2 ----
    float* const p = yT;   // p[f][u], f = oc2*5+ph; yT dead
    for (int wt = wid; wt < U * 5; wt += 8) {
        int u = wt / 5, ph = wt - u * 5;
        float wr[16];
        #pragma unroll
        for (int ic = 0; ic < 16; ++ic) wr[ic] = w11s[(ic << 5) + lan];
        float bias = b11s[lan];
        float m = -3.4e38f;
        int h1 = min(3 * ph + 3, GRID_H);
        for (int h = 3 * ph; h < h1; ++h) {
            #pragma unroll
            for (int w = 0; w < 3; ++w) {
                const float* ar = a1 + u * (G * C31) + ((h * 3 + w) << 4);
                float s = bias;
                #pragma unroll
                for (int ic = 0; ic < 16; ++ic)
                    s += ar[ic] * wr[ic];        // broadcast (1 wf)
                m = fmaxf(m, lrelu(s));
            }
        }
        p[((lan * 5 + ph) << 2) + u] = m;
    }
    __syncthreads();

    // ---- FC 160->64 cooperative: warp=(o-half, f-quarter) ----
    float* const red = featC;                    // red[fq][o][u]; featC dead
    {
        int orr = wid & 1, fq = wid >> 1;
        int o = (orr << 5) + lan;
        float a0 = 0.f, s1 = 0.f, a2 = 0.f, a3 = 0.f;
        int f0 = fq * 40;
        #pragma unroll 8
        for (int f = f0; f < f0 + 40; ++f) {
            float  wv = __ldg(fcwT + (f << 6) + o);        // 1 line / warp
            float4 pv = *(const float4*)(p + (f << 2));    // uniform
            a0 += wv * pv.x; s1 += wv * pv.y;
            a2 += wv * pv.z; a3 += wv * pv.w;
        }
        *(float4*)(red + ((fq << 6) + o) * 4) = make_float4(a0, s1, a2, a3);
    }
    __syncthreads();
    {
        int u = tid >> 6, o = tid & 63;
        int b = b0 + u;
        if (b < batch) {
            float acc = __ldg(fcb + o);
            #pragma unroll
            for (int fq = 0; fq < 4; ++fq)
                acc += red[((fq << 6) + o) * 4 + u];
            out[b * SOCD + o] = lrelu(acc);
        }
    }
}

} // namespace

extern "C" void kernel_launch(void* const* d_in, const int* in_sizes, int n_in,
                              void* d_out, int out_size)
{
    const float* enc = (const float*)d_in[0];
    const int*   nb  = (const int*)  d_in[1];
    const int*   gp  = (const int*)  d_in[2];
    const float* w31 = (const float*)d_in[3];
    const float* b31 = (const float*)d_in[4];
    const float* w11 = (const float*)d_in[5];
    const float* b11 = (const float*)d_in[6];
    const float* fcw = (const float*)d_in[7];
    const float* fcb = (const float*)d_in[8];
    float* out = (float*)d_out;

    const int batch = in_sizes[1] / KN;               // 8192
    const int nveh  = in_sizes[0] / (ENC * TS);       // 100000

    extract_kernel<<<(nveh * 32 + 255) / 256, 256>>>(enc, nveh);
    prep_kernel<<<(FCD * SOCD + 255) / 256, 256>>>(w31, fcw);
    csp_kernel<<<(batch + U - 1) / U, 256>>>(nb, gp, b31, w11, b11, fcb, out, batch);
}

// round 10
// speedup vs baseline: 1.5596x; 1.5596x over previous
#include <cuda_runtime.h>

// Round 10: revert extraction (round-7 gather); rebalance + shrink conv.
//  - conv task = (ocg, ic-half): 8 tasks / 8 warps, 3 kh-accumulators,
//    single pass over feat (17 instr / 12 FFMA; max-warp conv instr halved).
//  - a1 assembly and pool vectorized float4.
//  - smem 42KB -> 5 blocks/SM, launch_bounds(256,5).
namespace {

constexpr int GRID_H = 13;
constexpr int GRID_W = 3;
constexpr int G      = GRID_H * GRID_W;   // 39
constexpr int ENC    = 128;
constexpr int TS     = 16;
constexpr int C31    = 16;
constexpr int C11    = 32;
constexpr int SOCD   = 64;
constexpr int KN     = 32;
constexpr int U      = 4;                 // batches per block
constexpr int FPITCH = 129;
constexpr int MAXJ   = U * KN;
constexpr int FCD    = 160;

__device__ __align__(16) float wT[3 * ENC * C31];     // [kh][ic][oc16]
__device__ __align__(16) float fcwT[FCD * SOCD];      // [f][o]

__device__ __forceinline__ float lrelu(float x) { return x > 0.0f ? x : 0.1f * x; }

__global__ void prep_kernel(const float* __restrict__ w31,
                            const float* __restrict__ fcw)
{
    int i = blockIdx.x * 256 + threadIdx.x;
    if (i < 3 * ENC * C31) {
        int kh = i >> 11;
        int r  = i & 2047;
        int ic = r >> 4, oc = r & 15;
        wT[i] = w31[(oc * ENC + ic) * 3 + kh];
    }
    if (i < FCD * SOCD) {
        int f = i >> 6, o = i & 63;
        fcwT[i] = fcw[o * FCD + f];
    }
}

__global__ __launch_bounds__(256, 5)
void csp_kernel(const float* __restrict__ enc,   // [N_VEH,128,16]
                const int*   __restrict__ nb,    // [B,32]
                const int*   __restrict__ gp,    // [N_VEH,2]
                const float* __restrict__ b31,   // [16]
                const float* __restrict__ w11,   // [32,16]
                const float* __restrict__ b11,   // [32]
                const float* __restrict__ fcb,   // [64]
                float*       __restrict__ out,   // [B,64]
                int batch)
{
    __shared__ __align__(16) float featC[32 * FPITCH];   // 16512B; later red[4][64][4]
    __shared__ __align__(16) float yT[2 * 32 * 3 * C31]; // 12288B; later p[160][4]
    __shared__ __align__(16) float a1[U * G * C31];      // 9984B; winner ints at start
    __shared__ __align__(16) float w11s[C31 * C11];      // [ic][oc]
    __shared__ __align__(16) float b31s[C31];
    __shared__ float b11s[C11];
    __shared__ int   jOf[U * G];
    __shared__ int   vehG[MAXJ];
    __shared__ int   totCnt;

    const int b0  = blockIdx.x * U;
    const int tid = threadIdx.x;
    const int wid = tid >> 5;
    const int lan = tid & 31;

    // ---- stage small weights / init ----
    for (int i = tid; i < C31 * C11; i += 256) {
        int ic = i >> 5, oc = i & 31;
        w11s[i] = __ldg(w11 + oc * C31 + ic);
    }
    if (tid < C31) b31s[tid] = __ldg(b31 + tid);
    if (tid < C11) b11s[tid] = __ldg(b11 + tid);
    if (tid < U * G) jOf[tid] = -1;
    if (tid == 0) totCnt = 0;
    int* winner = (int*)a1;
    if (tid < U * G) winner[tid] = -1;
    __syncthreads();

    // ---- winners per cell ----
    if (tid < U * KN) {
        int u = tid >> 5, k = tid & 31;
        int b = b0 + u;
        if (b < batch) {
            int v = nb[b * KN + k];
            int x = __ldg(gp + 2 * v), yy = __ldg(gp + 2 * v + 1);
            if (x >= 0 && x < GRID_H && yy >= 0 && yy < GRID_W)
                atomicMax(&winner[u * G + x * GRID_W + yy], k);
        }
    }
    __syncthreads();
    if (tid < U * G) {
        int w = winner[tid];
        if (w >= 0) {
            int u = tid / G;
            int v = nb[(b0 + u) * KN + w];
            int j = atomicAdd(&totCnt, 1);
            jOf[tid] = j;
            vehG[j]  = v;
        }
    }
    __syncthreads();
    const int tot    = totCnt;
    const int ntiles = (tot + 31) >> 5;

    // ---- init a1 = bias (float4; winner scratch dead) ----
    {
        const float4* bv = (const float4*)b31s;
        float4* a1v = (float4*)a1;
        for (int e = tid; e < U * G * 4; e += 256)
            a1v[e] = bv[e & 3];
    }
    __syncthreads();

    // ---- tiles: gather -> conv3x1 (8 balanced tasks) -> accumulate a1 ----
    for (int t = 0; t < ntiles; ++t) {
        const int  jBase = t << 5;
        const int  nT    = min(32, tot - jBase);
        const bool last  = (t == ntiles - 1);

        for (int i = tid; i < (nT << 7); i += 256) {
            int s = i >> 7, ic = i & 127;
            int v = vehG[jBase + s];
            featC[s * FPITCH + ic] =
                __ldg(enc + (size_t)v * (ENC * TS) + ic * TS + (TS - 1));
        }
        __syncthreads();

        // conv: warp = (ocg, ih). lane = slot. 3 kh-accumulators, one feat pass.
        {
            const int ocg = wid & 3;
            const int ih  = wid >> 2;             // ic half: [64*ih, 64*ih+64)
            const float*  fr = featC + lan * FPITCH + (ih << 6);
            const float4* w0 = (const float4*)wT + ((ih << 6) << 2) + ocg;          // kh=0
            const float4* w1 = (const float4*)wT + 512 + ((ih << 6) << 2) + ocg;    // kh=1
            const float4* w2 = (const float4*)wT + 1024 + ((ih << 6) << 2) + ocg;   // kh=2
            float4 ac0 = make_float4(0.f, 0.f, 0.f, 0.f);
            float4 ac1 = make_float4(0.f, 0.f, 0.f, 0.f);
            float4 ac2 = make_float4(0.f, 0.f, 0.f, 0.f);
            #pragma unroll 8
            for (int j = 0; j < 64; ++j) {
                float  f  = fr[j];
                float4 v0 = __ldg(w0 + (j << 2));   // uniform across lanes
                float4 v1 = __ldg(w1 + (j << 2));
                float4 v2 = __ldg(w2 + (j << 2));
                ac0.x += f * v0.x; ac0.y += f * v0.y; ac0.z += f * v0.z; ac0.w += f * v0.w;
                ac1.x += f * v1.x; ac1.y += f * v1.y; ac1.z += f * v1.z; ac1.w += f * v1.w;
                ac2.x += f * v2.x; ac2.y += f * v2.y; ac2.z += f * v2.z; ac2.w += f * v2.w;
            }
            if (lan < nT) {
                float4* yb = (float4*)yT + (((ih << 5) + lan) * 3 << 2) + ocg;
                yb[0] = ac0; yb[4] = ac1; yb[8] = ac2;   // [kh]*4 float4 stride
            }
        }
        __syncthreads();

        // accumulate tile partials into a1 (float4, both ic-halves; deterministic)
        for (int e = tid; e < U * G * 4; e += 256) {
            int u   = e / (G * 4);
            int r   = e - u * (G * 4);
            int pos = r >> 2, g = r & 3;
            int h = pos / 3, w = pos - h * 3;
            float4 val = ((float4*)a1)[e];
            #pragma unroll
            for (int dh = -1; dh <= 1; ++dh) {
                int hh = h + dh;
                if ((unsigned)hh < (unsigned)GRID_H) {
                    int j = jOf[u * G + hh * 3 + w];
                    int s = j - jBase;
                    if (s >= 0 && s < nT) {
                        int kh = dh + 1;
                        float4 y0 = ((const float4*)yT)[((      s)  * 3 + kh) * 4 + g];
                        float4 y1 = ((const float4*)yT)[((32 +  s)  * 3 + kh) * 4 + g];
                        val.x += y0.x + y1.x; val.y += y0.y + y1.y;
                        val.z += y0.z + y1.z; val.w += y0.w + y1.w;
                    }
                }
            }
            if (last) {
                val.x = lrelu(val.x); val.y = lrelu(val.y);
                val.z = lrelu(val.z); val.w = lrelu(val.w);
            }
            ((float4*)a1)[e] = val;
        }
        __syncthreads();
    }
    if (ntiles == 0) {
        for (int e = tid; e < U * G * 4; e += 256) {
            float4 v = ((float4*)a1)[e];
            v.x = lrelu(v.x); v.y = lrelu(v.y); v.z = lrelu(v.z); v.w = lrelu(v.w);
            ((float4*)a1)[e] = v;
        }
        __syncthreads();
    }

    // ---- conv1x1 + lrelu + 3x3/3 maxpool. warp-task=(u,ph), lane=oc2; float4 a1 reads ----
    float* const p = yT;   // p[f][u], f = oc2*5+ph; yT dead
    for (int wt = wid; wt < U * 5; wt += 8) {
        int u = wt / 5, ph = wt - u * 5;
        float wr[16];
        #pragma unroll
        for (int ic = 0; ic < 16; ++ic) wr[ic] = w11s[(ic << 5) + lan];
        float bias = b11s[lan];
        float m = -3.4e38f;
        int h1 = min(3 * ph + 3, GRID_H);
        for (int h = 3 * ph; h < h1; ++h) {
            #pragma unroll
            for (int w = 0; w < 3; ++w) {
                const float4* ar = (const float4*)(a1 + u * (G * C31) + ((h * 3 + w) << 4));
                float4 q0 = ar[0], q1 = ar[1], q2 = ar[2], q3 = ar[3];
                float s = bias
                    + q0.x * wr[0]  + q0.y * wr[1]  + q0.z * wr[2]  + q0.w * wr[3]
                    + q1.x * wr[4]  + q1.y * wr[5]  + q1.z * wr[6]  + q1.w * wr[7]
                    + q2.x * wr[8]  + q2.y * wr[9]  + q2.z * wr[10] + q2.w * wr[11]
                    + q3.x * wr[12] + q3.y * wr[13] + q3.z * wr[14] + q3.w * wr[15];
                m = fmaxf(m, lrelu(s));
            }
        }
        p[((lan * 5 + ph) << 2) + u] = m;
    }
    __syncthreads();

    // ---- FC 160->64 cooperative: warp=(o-half, f-quarter) ----
    float* const red = featC;                    // red[fq][o][u]; featC dead
    {
        int orr = wid & 1, fq = wid >> 1;
        int o = (orr << 5) + lan;
        float a0 = 0.f, s1 = 0.f, a2 = 0.f, a3 = 0.f;
        int f0 = fq * 40;
        #pragma unroll 8
        for (int f = f0; f < f0 + 40; ++f) {
            float  wv = __ldg(fcwT + (f << 6) + o);        // 1 line / warp
            float4 pv = *(const float4*)(p + (f << 2));    // uniform
            a0 += wv * pv.x; s1 += wv * pv.y;
            a2 += wv * pv.z; a3 += wv * pv.w;
        }
        *(float4*)(red + ((fq << 6) + o) * 4) = make_float4(a0, s1, a2, a3);
    }
    __syncthreads();
    {
        int u = tid >> 6, o = tid & 63;
        int b = b0 + u;
        if (b < batch) {
            float acc = __ldg(fcb + o);
            #pragma unroll
            for (int fq = 0; fq < 4; ++fq)
                acc += red[((fq << 6) + o) * 4 + u];
            out[b * SOCD + o] = lrelu(acc);
        }
    }
}

} // namespace

extern "C" void kernel_launch(void* const* d_in, const int* in_sizes, int n_in,
                              void* d_out, int out_size)
{
    const float* enc = (const float*)d_in[0];
    const int*   nb  = (const int*)  d_in[1];
    const int*   gp  = (const int*)  d_in[2];
    const float* w31 = (const float*)d_in[3];
    const float* b31 = (const float*)d_in[4];
    const float* w11 = (const float*)d_in[5];
    const float* b11 = (const float*)d_in[6];
    const float* fcw = (const float*)d_in[7];
    const float* fcb = (const float*)d_in[8];
    float* out = (float*)d_out;

    const int batch = in_sizes[1] / KN;   // 8192

    prep_kernel<<<(FCD * SOCD + 255) / 256, 256>>>(w31, fcw);
    csp_kernel<<<(batch + U - 1) / U, 256>>>(enc, nb, gp, b31, w11, b11, fcb, out, batch);
}